// round 3
// baseline (speedup 1.0000x reference)
#include <cuda_runtime.h>

#define N_USERS 100000
#define N_ITEMS 200000
#define N_NODESC 300000
#define EMB 64
#define NLAYERS 3
#define N_EDGESC 9600000
#define BATCHC 4096
#define NEG_SLOPE 0.2f

// ---------------- device scratch (no mallocs allowed) ----------------
__device__ float g_ego[N_NODESC * EMB];     // current node embeddings (updated per layer)
__device__ float g_neigh[N_NODESC * EMB];   // aggregated neighbor embeddings
__device__ int   g_cnt[N_NODESC];           // per-row edge counts
__device__ int   g_rowptr[N_NODESC + 1];    // CSR row pointers
__device__ int   g_cursor[N_NODESC];        // scatter cursors
__device__ int   g_ccol[N_EDGESC];          // CSR column indices
__device__ float g_cval[N_EDGESC];          // CSR edge values
__device__ int   g_bsum[512];               // scan block sums

// ---------------- CSR build ----------------
__global__ void zero_cnt_kernel() {
    int i = blockIdx.x * blockDim.x + threadIdx.x;
    if (i < N_NODESC) g_cnt[i] = 0;
}

__global__ void hist_kernel(const int* __restrict__ row) {
    int e = blockIdx.x * blockDim.x + threadIdx.x;
    if (e < N_EDGESC) atomicAdd(&g_cnt[row[e]], 1);
}

// per-block inclusive scan of counts (1024 elems / block)
__global__ void scan1_kernel() {
    __shared__ int s[1024];
    int t = threadIdx.x;
    int i = blockIdx.x * 1024 + t;
    int v = (i < N_NODESC) ? g_cnt[i] : 0;
    s[t] = v;
    __syncthreads();
#pragma unroll
    for (int off = 1; off < 1024; off <<= 1) {
        int x = (t >= off) ? s[t - off] : 0;
        __syncthreads();
        s[t] += x;
        __syncthreads();
    }
    if (i < N_NODESC) g_rowptr[i + 1] = s[t];  // local inclusive, offset added later
    if (t == 1023) g_bsum[blockIdx.x] = s[1023];
}

// exclusive scan of block sums (single block; nb <= 512)
__global__ void scan2_kernel(int nb) {
    __shared__ int s[512];
    int t = threadIdx.x;
    int v = (t < nb) ? g_bsum[t] : 0;
    s[t] = v;
    __syncthreads();
#pragma unroll
    for (int off = 1; off < 512; off <<= 1) {
        int x = (t >= off) ? s[t - off] : 0;
        __syncthreads();
        s[t] += x;
        __syncthreads();
    }
    if (t < nb) g_bsum[t] = s[t] - v;  // exclusive
}

__global__ void scan3_kernel() {
    int i = blockIdx.x * blockDim.x + threadIdx.x;
    if (i >= N_NODESC) return;
    int incl = g_rowptr[i + 1] + g_bsum[i >> 10];
    g_rowptr[i + 1] = incl;
    g_cursor[i] = incl - g_cnt[i];  // exclusive start for scatter
    if (i == 0) g_rowptr[0] = 0;
}

__global__ void scatter_kernel(const int* __restrict__ row,
                               const int* __restrict__ col,
                               const float* __restrict__ val) {
    int e = blockIdx.x * blockDim.x + threadIdx.x;
    if (e >= N_EDGESC) return;
    int r = row[e];
    int p = atomicAdd(&g_cursor[r], 1);
    g_ccol[p] = col[e];
    g_cval[p] = val[e];
}

// ---------------- embedding init ----------------
__global__ void copy_ego_kernel(const float4* __restrict__ ue,
                                const float4* __restrict__ ie) {
    int i = blockIdx.x * blockDim.x + threadIdx.x;  // over N_NODESC*16 float4s
    if (i >= N_NODESC * (EMB / 4)) return;
    float4* ego4 = reinterpret_cast<float4*>(g_ego);
    const int ucount = N_USERS * (EMB / 4);
    ego4[i] = (i < ucount) ? ue[i] : ie[i - ucount];
}

// ---------------- per-layer aggregation: neigh = segment_sum(ego[col]*val, row) ----------------
__global__ void aggregate_kernel() {
    int gid = blockIdx.x * blockDim.x + threadIdx.x;
    int node = gid >> 4;
    if (node >= N_NODESC) return;
    int g = gid & 15;
    const float4* ego4 = reinterpret_cast<const float4*>(g_ego);
    float4* neigh4 = reinterpret_cast<float4*>(g_neigh);

    int beg = g_rowptr[node];
    int end = g_rowptr[node + 1];
    float4 acc = make_float4(0.f, 0.f, 0.f, 0.f);
#pragma unroll 4
    for (int e = beg; e < end; e++) {
        int c = g_ccol[e];
        float v = g_cval[e];
        float4 x = ego4[c * 16 + g];
        acc.x += v * x.x;
        acc.y += v * x.y;
        acc.z += v * x.z;
        acc.w += v * x.w;
    }
    neigh4[node * 16 + g] = acc;
}

// ---------------- per-layer transform:
// ego = l2norm(leaky_relu(neigh@Wgc + (ego*neigh)@Wbi + bgc + bbi)) ----------------
__global__ void transform_kernel(const float* __restrict__ Wgc,
                                 const float* __restrict__ bgc,
                                 const float* __restrict__ Wbi,
                                 const float* __restrict__ bbi,
                                 int layer) {
    __shared__ float sW1[EMB * EMB];
    __shared__ float sW2[EMB * EMB];
    __shared__ float sb[EMB];

    const float* w1g = Wgc + layer * EMB * EMB;
    const float* w2g = Wbi + layer * EMB * EMB;
    for (int i = threadIdx.x; i < EMB * EMB; i += blockDim.x) {
        sW1[i] = w1g[i];
        sW2[i] = w2g[i];
    }
    if (threadIdx.x < EMB)
        sb[threadIdx.x] = bgc[layer * EMB + threadIdx.x] + bbi[layer * EMB + threadIdx.x];
    __syncthreads();

    int gid = blockIdx.x * blockDim.x + threadIdx.x;
    int node = gid >> 4;
    if (node >= N_NODESC) return;
    int g = gid & 15;

    float4* ego4 = reinterpret_cast<float4*>(g_ego);
    const float4* neigh4 = reinterpret_cast<const float4*>(g_neigh);

    float4 x1 = neigh4[node * 16 + g];
    float4 e0 = ego4[node * 16 + g];
    float x1v[4] = {x1.x, x1.y, x1.z, x1.w};
    float x2v[4] = {e0.x * x1.x, e0.y * x1.y, e0.z * x1.z, e0.w * x1.w};

    float4 acc = *reinterpret_cast<const float4*>(&sb[g * 4]);

    const unsigned mask = 0xffffffffu;
#pragma unroll
    for (int k = 0; k < EMB; k++) {
        int src = k >> 2;
        float a1 = __shfl_sync(mask, x1v[k & 3], src, 16);
        float a2 = __shfl_sync(mask, x2v[k & 3], src, 16);
        float4 w1 = *reinterpret_cast<const float4*>(&sW1[k * EMB + g * 4]);
        float4 w2 = *reinterpret_cast<const float4*>(&sW2[k * EMB + g * 4]);
        acc.x += a1 * w1.x + a2 * w2.x;
        acc.y += a1 * w1.y + a2 * w2.y;
        acc.z += a1 * w1.z + a2 * w2.z;
        acc.w += a1 * w1.w + a2 * w2.w;
    }

    // leaky relu
    acc.x = (acc.x >= 0.f) ? acc.x : NEG_SLOPE * acc.x;
    acc.y = (acc.y >= 0.f) ? acc.y : NEG_SLOPE * acc.y;
    acc.z = (acc.z >= 0.f) ? acc.z : NEG_SLOPE * acc.z;
    acc.w = (acc.w >= 0.f) ? acc.w : NEG_SLOPE * acc.w;

    // l2 normalize across the 64 dims (16 lanes x 4)
    float s = acc.x * acc.x + acc.y * acc.y + acc.z * acc.z + acc.w * acc.w;
#pragma unroll
    for (int off = 8; off >= 1; off >>= 1)
        s += __shfl_xor_sync(mask, s, off, 16);
    float n = sqrtf(s);
    float scale = 1.0f / fmaxf(n, 1e-12f);

    acc.x *= scale; acc.y *= scale; acc.z *= scale; acc.w *= scale;
    ego4[node * 16 + g] = acc;
}

// ---------------- output gather for one stage ----------------
__global__ void gather_out_kernel(const int* __restrict__ users,
                                  const int* __restrict__ pos,
                                  const int* __restrict__ neg,
                                  float* __restrict__ out,
                                  int stage) {
    int gid = blockIdx.x * blockDim.x + threadIdx.x;  // 3*BATCH*16 threads
    int r = gid >> 4;
    if (r >= 3 * BATCHC) return;
    int g = gid & 15;
    int node;
    if (r < BATCHC) node = users[r];
    else if (r < 2 * BATCHC) node = N_USERS + pos[r - BATCHC];
    else node = N_USERS + neg[r - 2 * BATCHC];

    const float4* ego4 = reinterpret_cast<const float4*>(g_ego);
    float4 v = ego4[node * 16 + g];
    *reinterpret_cast<float4*>(&out[(size_t)r * (4 * EMB) + stage * EMB + g * 4]) = v;
}

// ---------------- launch ----------------
extern "C" void kernel_launch(void* const* d_in, const int* in_sizes, int n_in,
                              void* d_out, int out_size) {
    const int*   edge_row = (const int*)d_in[0];
    const int*   edge_col = (const int*)d_in[1];
    const float* edge_val = (const float*)d_in[2];
    const float* user_emb = (const float*)d_in[3];
    const float* item_emb = (const float*)d_in[4];
    const float* W_gc     = (const float*)d_in[5];
    const float* b_gc     = (const float*)d_in[6];
    const float* W_bi     = (const float*)d_in[7];
    const float* b_bi     = (const float*)d_in[8];
    const int*   users    = (const int*)d_in[9];
    const int*   pos      = (const int*)d_in[10];
    const int*   neg      = (const int*)d_in[11];
    float* out = (float*)d_out;

    const int T = 256;
    const int nbNodes = (N_NODESC + T - 1) / T;
    const int nbEdges = (N_EDGESC + T - 1) / T;
    const int scanBlocks = (N_NODESC + 1023) / 1024;  // 293
    const int nbNode16 = (N_NODESC * 16) / T;         // 18750 (exact)
    const int nbGather = (3 * BATCHC * 16 + T - 1) / T;

    // CSR build
    zero_cnt_kernel<<<nbNodes, T>>>();
    hist_kernel<<<nbEdges, T>>>(edge_row);
    scan1_kernel<<<scanBlocks, 1024>>>();
    scan2_kernel<<<1, 512>>>(scanBlocks);
    scan3_kernel<<<nbNodes, T>>>();
    scatter_kernel<<<nbEdges, T>>>(edge_row, edge_col, edge_val);

    // init ego
    copy_ego_kernel<<<nbNode16, T>>>((const float4*)user_emb, (const float4*)item_emb);

    // stage 0 output
    gather_out_kernel<<<nbGather, T>>>(users, pos, neg, out, 0);

    // 3 layers
    for (int k = 0; k < NLAYERS; k++) {
        aggregate_kernel<<<nbNode16, T>>>();
        transform_kernel<<<nbNode16, T>>>(W_gc, b_gc, W_bi, b_bi, k);
        gather_out_kernel<<<nbGather, T>>>(users, pos, neg, out, k + 1);
    }
}

// round 4
// speedup vs baseline: 1.4262x; 1.4262x over previous
#include <cuda_runtime.h>
#include <cuda_fp16.h>

#define N_USERS 100000
#define N_ITEMS 200000
#define N_NODESC 300000
#define EMB 64
#define NLAYERS 3
#define N_EDGESC 9600000
#define BATCHC 4096
#define NEG_SLOPE 0.2f

// ---------------- device scratch (no mallocs allowed) ----------------
__device__ float g_ego[N_NODESC * EMB];     // fp32 master node embeddings
__device__ uint2 g_egoH[N_NODESC * 16];     // fp16 mirror (4 halfs per uint2) for gathers
__device__ float g_neigh[N_NODESC * EMB];   // aggregated neighbor embeddings
__device__ int   g_cnt[N_NODESC];
__device__ int   g_rowptr[N_NODESC + 1];
__device__ int   g_cursor[N_NODESC];
__device__ int   g_ccol[N_EDGESC];
__device__ float g_cval[N_EDGESC];
__device__ int   g_bsum[512];

// ---------------- f32x2 helpers (sm_103a packed fp32) ----------------
__device__ __forceinline__ void fma2(unsigned long long& d, unsigned long long a,
                                     unsigned long long b) {
    asm("fma.rn.f32x2 %0, %1, %2, %0;" : "+l"(d) : "l"(a), "l"(b));
}
__device__ __forceinline__ unsigned long long pk2(float lo, float hi) {
    unsigned long long r;
    asm("mov.b64 %0, {%1, %2};" : "=l"(r) : "f"(lo), "f"(hi));
    return r;
}
__device__ __forceinline__ float2 upk2(unsigned long long v) {
    float lo, hi;
    asm("mov.b64 {%0, %1}, %2;" : "=f"(lo), "=f"(hi) : "l"(v));
    return make_float2(lo, hi);
}

// ---------------- CSR build ----------------
__global__ void zero_cnt_kernel() {
    int i = blockIdx.x * blockDim.x + threadIdx.x;
    if (i < N_NODESC) g_cnt[i] = 0;
}

__global__ void hist_kernel(const int* __restrict__ row) {
    int e = blockIdx.x * blockDim.x + threadIdx.x;
    if (e < N_EDGESC) atomicAdd(&g_cnt[row[e]], 1);
}

__global__ void scan1_kernel() {
    __shared__ int s[1024];
    int t = threadIdx.x;
    int i = blockIdx.x * 1024 + t;
    int v = (i < N_NODESC) ? g_cnt[i] : 0;
    s[t] = v;
    __syncthreads();
#pragma unroll
    for (int off = 1; off < 1024; off <<= 1) {
        int x = (t >= off) ? s[t - off] : 0;
        __syncthreads();
        s[t] += x;
        __syncthreads();
    }
    if (i < N_NODESC) g_rowptr[i + 1] = s[t];
    if (t == 1023) g_bsum[blockIdx.x] = s[1023];
}

__global__ void scan2_kernel(int nb) {
    __shared__ int s[512];
    int t = threadIdx.x;
    int v = (t < nb) ? g_bsum[t] : 0;
    s[t] = v;
    __syncthreads();
#pragma unroll
    for (int off = 1; off < 512; off <<= 1) {
        int x = (t >= off) ? s[t - off] : 0;
        __syncthreads();
        s[t] += x;
        __syncthreads();
    }
    if (t < nb) g_bsum[t] = s[t] - v;
}

__global__ void scan3_kernel() {
    int i = blockIdx.x * blockDim.x + threadIdx.x;
    if (i >= N_NODESC) return;
    int incl = g_rowptr[i + 1] + g_bsum[i >> 10];
    g_rowptr[i + 1] = incl;
    g_cursor[i] = incl - g_cnt[i];
    if (i == 0) g_rowptr[0] = 0;
}

__global__ void scatter_kernel(const int* __restrict__ row,
                               const int* __restrict__ col,
                               const float* __restrict__ val) {
    int e = blockIdx.x * blockDim.x + threadIdx.x;
    if (e >= N_EDGESC) return;
    int r = row[e];
    int p = atomicAdd(&g_cursor[r], 1);
    g_ccol[p] = col[e];
    g_cval[p] = val[e];
}

// ---------------- embedding init (fp32 + fp16 mirror) ----------------
__global__ void copy_ego_kernel(const float4* __restrict__ ue,
                                const float4* __restrict__ ie) {
    int i = blockIdx.x * blockDim.x + threadIdx.x;
    if (i >= N_NODESC * (EMB / 4)) return;
    float4* ego4 = reinterpret_cast<float4*>(g_ego);
    const int ucount = N_USERS * (EMB / 4);
    float4 v = (i < ucount) ? ue[i] : ie[i - ucount];
    ego4[i] = v;
    __half2 h0 = __float22half2_rn(make_float2(v.x, v.y));
    __half2 h1 = __float22half2_rn(make_float2(v.z, v.w));
    uint2 p;
    p.x = *reinterpret_cast<unsigned*>(&h0);
    p.y = *reinterpret_cast<unsigned*>(&h1);
    g_egoH[i] = p;
}

// ---------------- aggregation: neigh = segment_sum(egoH[col]*val, row) ----------------
__global__ void aggregate_kernel() {
    int gid = blockIdx.x * blockDim.x + threadIdx.x;
    int node = gid >> 4;
    if (node >= N_NODESC) return;
    int g = gid & 15;
    float4* neigh4 = reinterpret_cast<float4*>(g_neigh);

    int beg = g_rowptr[node];
    int end = g_rowptr[node + 1];
    float4 acc = make_float4(0.f, 0.f, 0.f, 0.f);
#pragma unroll 4
    for (int e = beg; e < end; e++) {
        int c = g_ccol[e];
        float v = g_cval[e];
        uint2 p = g_egoH[c * 16 + g];
        float2 f0 = __half22float2(*reinterpret_cast<__half2*>(&p.x));
        float2 f1 = __half22float2(*reinterpret_cast<__half2*>(&p.y));
        acc.x += v * f0.x;
        acc.y += v * f0.y;
        acc.z += v * f1.x;
        acc.w += v * f1.y;
    }
    neigh4[node * 16 + g] = acc;
}

// ---------------- transform: 2 nodes/thread, interleaved weight pairs, f32x2 FMA
// ego = l2norm(leaky_relu(neigh@Wgc + (ego*neigh)@Wbi + bgc + bbi)) ----------------
__global__ void transform_kernel(const float* __restrict__ Wgc,
                                 const float* __restrict__ bgc,
                                 const float* __restrict__ Wbi,
                                 const float* __restrict__ bbi,
                                 int layer) {
    __shared__ float sWp[EMB * EMB * 2];  // [k][j*2 + {gc,bi}]  (32 KB)
    __shared__ float sb[EMB];

    const float* w1g = Wgc + layer * EMB * EMB;
    const float* w2g = Wbi + layer * EMB * EMB;
    for (int i = threadIdx.x; i < EMB * EMB; i += blockDim.x) {
        int k = i >> 6, j = i & 63;
        sWp[(k << 7) + (j << 1)]     = w1g[i];
        sWp[(k << 7) + (j << 1) + 1] = w2g[i];
    }
    if (threadIdx.x < EMB)
        sb[threadIdx.x] = bgc[layer * EMB + threadIdx.x] + bbi[layer * EMB + threadIdx.x];
    __syncthreads();

    int gid = blockIdx.x * blockDim.x + threadIdx.x;
    int tpi = gid >> 4;                 // thread-pair index (2 nodes per thread)
    if (tpi >= N_NODESC / 2) return;    // grid is exact; guard never trips
    int g = gid & 15;
    int l = threadIdx.x & 31;
    int nA = tpi * 2, nB = nA + 1;

    const float4* ego4 = reinterpret_cast<const float4*>(g_ego);
    const float4* neigh4 = reinterpret_cast<const float4*>(g_neigh);

    float4 xa = neigh4[nA * 16 + g];
    float4 ea = ego4[nA * 16 + g];
    float4 xb = neigh4[nB * 16 + g];
    float4 eb = ego4[nB * 16 + g];

    // pre-packed (x1, x2) broadcast sources: x1 = neigh, x2 = ego*neigh
    unsigned long long pxA[4], pxB[4];
    pxA[0] = pk2(xa.x, ea.x * xa.x); pxA[1] = pk2(xa.y, ea.y * xa.y);
    pxA[2] = pk2(xa.z, ea.z * xa.z); pxA[3] = pk2(xa.w, ea.w * xa.w);
    pxB[0] = pk2(xb.x, eb.x * xb.x); pxB[1] = pk2(xb.y, eb.y * xb.y);
    pxB[2] = pk2(xb.z, eb.z * xb.z); pxB[3] = pk2(xb.w, eb.w * xb.w);

    // output columns handled by this lane (same for both nodes)
    int c0 = l, c1 = l ^ 16, c2 = l + 32, c3 = (l ^ 16) + 32;

    // accumulators: (gc-part incl. bias, bi-part)
    unsigned long long aA0 = pk2(sb[c0], 0.f), aA1 = pk2(sb[c1], 0.f);
    unsigned long long aA2 = pk2(sb[c2], 0.f), aA3 = pk2(sb[c3], 0.f);
    unsigned long long aB0 = aA0, aB1 = aA1, aB2 = aA2, aB3 = aA3;

    const unsigned mask = 0xffffffffu;
#pragma unroll
    for (int k = 0; k < EMB; k++) {
        // conflict-free weight loads: lane l gets pairs for j=l and j=l+32
        const unsigned long long* wr =
            reinterpret_cast<const unsigned long long*>(sWp + (k << 7));
        unsigned long long v0 = wr[l];
        unsigned long long v1 = wr[l + 32];
        // partner exchange recovers j=l^16 and j=(l^16)+32
        unsigned long long o0 = __shfl_xor_sync(mask, v0, 16);
        unsigned long long o1 = __shfl_xor_sync(mask, v1, 16);

        unsigned long long pa = __shfl_sync(mask, pxA[k & 3], k >> 2, 16);
        unsigned long long pb = __shfl_sync(mask, pxB[k & 3], k >> 2, 16);

        fma2(aA0, pa, v0); fma2(aA1, pa, o0); fma2(aA2, pa, v1); fma2(aA3, pa, o1);
        fma2(aB0, pb, v0); fma2(aB1, pb, o0); fma2(aB2, pb, v1); fma2(aB3, pb, o1);
    }

    // epilogue: combine halves, leaky relu, l2 norm per node, store fp32 + fp16
    float oA[4], oB[4];
    {
        float2 t;
        t = upk2(aA0); oA[0] = t.x + t.y;
        t = upk2(aA1); oA[1] = t.x + t.y;
        t = upk2(aA2); oA[2] = t.x + t.y;
        t = upk2(aA3); oA[3] = t.x + t.y;
        t = upk2(aB0); oB[0] = t.x + t.y;
        t = upk2(aB1); oB[1] = t.x + t.y;
        t = upk2(aB2); oB[2] = t.x + t.y;
        t = upk2(aB3); oB[3] = t.x + t.y;
    }
    float sA = 0.f, sB = 0.f;
#pragma unroll
    for (int m = 0; m < 4; m++) {
        oA[m] = (oA[m] >= 0.f) ? oA[m] : NEG_SLOPE * oA[m];
        oB[m] = (oB[m] >= 0.f) ? oB[m] : NEG_SLOPE * oB[m];
        sA += oA[m] * oA[m];
        sB += oB[m] * oB[m];
    }
#pragma unroll
    for (int off = 8; off >= 1; off >>= 1) {
        sA += __shfl_xor_sync(mask, sA, off, 16);
        sB += __shfl_xor_sync(mask, sB, off, 16);
    }
    float scA = 1.0f / fmaxf(sqrtf(sA), 1e-12f);
    float scB = 1.0f / fmaxf(sqrtf(sB), 1e-12f);

    float* rowA = g_ego + nA * EMB;
    float* rowB = g_ego + nB * EMB;
    __half* hA = reinterpret_cast<__half*>(g_egoH) + nA * EMB;
    __half* hB = reinterpret_cast<__half*>(g_egoH) + nB * EMB;
    int cc[4] = {c0, c1, c2, c3};
#pragma unroll
    for (int m = 0; m < 4; m++) {
        float va = oA[m] * scA;
        float vb = oB[m] * scB;
        rowA[cc[m]] = va;
        rowB[cc[m]] = vb;
        hA[cc[m]] = __float2half_rn(va);
        hB[cc[m]] = __float2half_rn(vb);
    }
}

// ---------------- output gather for one stage ----------------
__global__ void gather_out_kernel(const int* __restrict__ users,
                                  const int* __restrict__ pos,
                                  const int* __restrict__ neg,
                                  float* __restrict__ out,
                                  int stage) {
    int gid = blockIdx.x * blockDim.x + threadIdx.x;
    int r = gid >> 4;
    if (r >= 3 * BATCHC) return;
    int g = gid & 15;
    int node;
    if (r < BATCHC) node = users[r];
    else if (r < 2 * BATCHC) node = N_USERS + pos[r - BATCHC];
    else node = N_USERS + neg[r - 2 * BATCHC];

    const float4* ego4 = reinterpret_cast<const float4*>(g_ego);
    float4 v = ego4[node * 16 + g];
    *reinterpret_cast<float4*>(&out[(size_t)r * (4 * EMB) + stage * EMB + g * 4]) = v;
}

// ---------------- launch ----------------
extern "C" void kernel_launch(void* const* d_in, const int* in_sizes, int n_in,
                              void* d_out, int out_size) {
    const int*   edge_row = (const int*)d_in[0];
    const int*   edge_col = (const int*)d_in[1];
    const float* edge_val = (const float*)d_in[2];
    const float* user_emb = (const float*)d_in[3];
    const float* item_emb = (const float*)d_in[4];
    const float* W_gc     = (const float*)d_in[5];
    const float* b_gc     = (const float*)d_in[6];
    const float* W_bi     = (const float*)d_in[7];
    const float* b_bi     = (const float*)d_in[8];
    const int*   users    = (const int*)d_in[9];
    const int*   pos      = (const int*)d_in[10];
    const int*   neg      = (const int*)d_in[11];
    float* out = (float*)d_out;

    const int T = 256;
    const int nbNodes = (N_NODESC + T - 1) / T;
    const int nbEdges = (N_EDGESC + T - 1) / T;
    const int scanBlocks = (N_NODESC + 1023) / 1024;   // 293
    const int nbNode16 = (N_NODESC * 16) / T;          // 18750 (exact)
    const int nbPair16 = ((N_NODESC / 2) * 16) / T;    // 9375 (exact)
    const int nbGather = (3 * BATCHC * 16 + T - 1) / T;

    // CSR build
    zero_cnt_kernel<<<nbNodes, T>>>();
    hist_kernel<<<nbEdges, T>>>(edge_row);
    scan1_kernel<<<scanBlocks, 1024>>>();
    scan2_kernel<<<1, 512>>>(scanBlocks);
    scan3_kernel<<<nbNodes, T>>>();
    scatter_kernel<<<nbEdges, T>>>(edge_row, edge_col, edge_val);

    // init ego (fp32 + fp16 mirror)
    copy_ego_kernel<<<nbNode16, T>>>((const float4*)user_emb, (const float4*)item_emb);

    // stage 0 output
    gather_out_kernel<<<nbGather, T>>>(users, pos, neg, out, 0);

    // 3 layers
    for (int k = 0; k < NLAYERS; k++) {
        aggregate_kernel<<<nbNode16, T>>>();
        transform_kernel<<<nbPair16, T>>>(W_gc, b_gc, W_bi, b_bi, k);
        gather_out_kernel<<<nbGather, T>>>(users, pos, neg, out, k + 1);
    }
}